// round 2
// baseline (speedup 1.0000x reference)
#include <cuda_runtime.h>

// Problem constants (fixed by the dataset)
#define NB      2
#define NATOMS  25000
#define NE      400000
#define DCH     128
#define NRBF    64

// Launch config
#define BLOCKS  296
#define TPB     256
#define WPB     (TPB/32)                 // 8 warps per block
#define TOTAL_WARPS (BLOCKS*WPB)         // 2368
#define WARPS_PER_BATCH (TOTAL_WARPS/NB) // 1184
#define CHUNK   340                      // 1184*340 = 402560 >= 400000

// Dynamic smem layout (floats)
//  W1s : 64*128  = 8192
//  W2s : 128*128 = 16384
//  rbf : 8 warps * 4 edges * 64  = 2048
//  h1  : 8 warps * 4 edges * 128 = 4096
#define SMEM_FLOATS (8192 + 16384 + 2048 + 4096)   // 30720 floats = 122880 B

__device__ __forceinline__ float ssp(float x) {
    // shifted softplus: log(1+exp(x)) - log(2), numerically stable
    float ax = fabsf(x);
    return fmaxf(x, 0.f) + __logf(1.f + __expf(-ax)) - 0.69314718056f;
}

__global__ __launch_bounds__(TPB, 1)
void cfconv_kernel(const float* __restrict__ atom,      // [B, N, D]
                   const float* __restrict__ dist,      // [B, E]
                   const int*   __restrict__ idx_j,     // [E]
                   const int*   __restrict__ seg_i,     // [E] sorted
                   const float* __restrict__ centers,   // [64]
                   const float* __restrict__ gammav,    // [64]
                   const float* __restrict__ W1,        // [64, 128]
                   const float* __restrict__ b1,        // [128]
                   const float* __restrict__ W2,        // [128, 128]
                   const float* __restrict__ b2,        // [128]
                   float*       __restrict__ out)       // [B, N, D], pre-zeroed
{
    extern __shared__ float sm[];
    float* W1s   = sm;                 // 8192
    float* W2s   = sm + 8192;          // 16384
    float* rbf_s = sm + 24576;         // 2048
    float* h1_s  = sm + 26624;         // 4096

    const int tid = threadIdx.x;
    for (int i = tid; i < NRBF*DCH; i += TPB) W1s[i] = W1[i];
    for (int i = tid; i < DCH*DCH;  i += TPB) W2s[i] = W2[i];
    __syncthreads();

    const int wib  = tid >> 5;
    const int lane = tid & 31;
    float* rbf_w = rbf_s + wib * (4*NRBF);
    float* h1_w  = h1_s  + wib * (4*DCH);
    const int c0 = lane * 4;

    const float4 bb1 = *(const float4*)(b1 + c0);
    const float4 bb2 = *(const float4*)(b2 + c0);
    const float c_lo = centers[lane],    c_hi = centers[lane+32];
    const float g_lo = gammav[lane],     g_hi = gammav[lane+32];

    const int  gw = blockIdx.x * WPB + wib;
    const int  b  = gw / WARPS_PER_BATCH;
    long e0    = (long)(gw % WARPS_PER_BATCH) * CHUNK;
    long e_end = e0 + CHUNK; if (e_end > NE) e_end = NE;

    const float* distb = dist + (size_t)b * NE;
    const float* atomb = atom + (size_t)b * NATOMS * DCH;
    float*       outb  = out  + (size_t)b * NATOMS * DCH;

    int   cur_seg = -1;
    float4 racc   = make_float4(0.f, 0.f, 0.f, 0.f);

    for (long base = e0; base < e_end; base += 4) {
        const int m = (int)((e_end - base) < 4 ? (e_end - base) : 4);

        // ---- RBF expansion into per-warp smem tile ----
        #pragma unroll
        for (int e = 0; e < 4; e++) {
            long ge = base + (e < m ? e : m - 1);
            float d  = distb[ge];
            float t0 = d - c_lo, t1 = d - c_hi;
            rbf_w[e*NRBF + lane]      = __expf(-g_lo * t0 * t0);
            rbf_w[e*NRBF + lane + 32] = __expf(-g_hi * t1 * t1);
        }
        __syncwarp();

        // ---- h1 = ssp(rbf @ W1 + b1) ----
        float4 acc[4];
        #pragma unroll
        for (int e = 0; e < 4; e++) acc[e] = make_float4(0.f, 0.f, 0.f, 0.f);

        for (int k = 0; k < NRBF; k += 4) {
            float4 w0 = *(const float4*)(W1s + (k+0)*DCH + c0);
            float4 w1 = *(const float4*)(W1s + (k+1)*DCH + c0);
            float4 w2 = *(const float4*)(W1s + (k+2)*DCH + c0);
            float4 w3 = *(const float4*)(W1s + (k+3)*DCH + c0);
            #pragma unroll
            for (int e = 0; e < 4; e++) {
                float4 r = *(const float4*)(rbf_w + e*NRBF + k);
                acc[e].x = fmaf(r.x,w0.x, fmaf(r.y,w1.x, fmaf(r.z,w2.x, fmaf(r.w,w3.x, acc[e].x))));
                acc[e].y = fmaf(r.x,w0.y, fmaf(r.y,w1.y, fmaf(r.z,w2.y, fmaf(r.w,w3.y, acc[e].y))));
                acc[e].z = fmaf(r.x,w0.z, fmaf(r.y,w1.z, fmaf(r.z,w2.z, fmaf(r.w,w3.z, acc[e].z))));
                acc[e].w = fmaf(r.x,w0.w, fmaf(r.y,w1.w, fmaf(r.z,w2.w, fmaf(r.w,w3.w, acc[e].w))));
            }
        }
        #pragma unroll
        for (int e = 0; e < 4; e++) {
            float4 h;
            h.x = ssp(acc[e].x + bb1.x);
            h.y = ssp(acc[e].y + bb1.y);
            h.z = ssp(acc[e].z + bb1.z);
            h.w = ssp(acc[e].w + bb1.w);
            *(float4*)(h1_w + e*DCH + c0) = h;
        }
        __syncwarp();

        // ---- filters = ssp(h1 @ W2 + b2) ----
        #pragma unroll
        for (int e = 0; e < 4; e++) acc[e] = make_float4(0.f, 0.f, 0.f, 0.f);

        for (int j = 0; j < DCH; j += 4) {
            float4 w0 = *(const float4*)(W2s + (j+0)*DCH + c0);
            float4 w1 = *(const float4*)(W2s + (j+1)*DCH + c0);
            float4 w2 = *(const float4*)(W2s + (j+2)*DCH + c0);
            float4 w3 = *(const float4*)(W2s + (j+3)*DCH + c0);
            #pragma unroll
            for (int e = 0; e < 4; e++) {
                float4 r = *(const float4*)(h1_w + e*DCH + j);
                acc[e].x = fmaf(r.x,w0.x, fmaf(r.y,w1.x, fmaf(r.z,w2.x, fmaf(r.w,w3.x, acc[e].x))));
                acc[e].y = fmaf(r.x,w0.y, fmaf(r.y,w1.y, fmaf(r.z,w2.y, fmaf(r.w,w3.y, acc[e].y))));
                acc[e].z = fmaf(r.x,w0.z, fmaf(r.y,w1.z, fmaf(r.z,w2.z, fmaf(r.w,w3.z, acc[e].z))));
                acc[e].w = fmaf(r.x,w0.w, fmaf(r.y,w1.w, fmaf(r.z,w2.w, fmaf(r.w,w3.w, acc[e].w))));
            }
        }

        float4 filt[4];
        #pragma unroll
        for (int e = 0; e < 4; e++) {
            filt[e].x = ssp(acc[e].x + bb2.x);
            filt[e].y = ssp(acc[e].y + bb2.y);
            filt[e].z = ssp(acc[e].z + bb2.z);
            filt[e].w = ssp(acc[e].w + bb2.w);
        }

        // ---- gather, multiply, run-length segment accumulate ----
        #pragma unroll
        for (int e = 0; e < 4; e++) {
            if (e >= m) break;
            long ge = base + e;
            int aj = idx_j[ge];
            int si = seg_i[ge];
            float4 f = *(const float4*)(atomb + (size_t)aj * DCH + c0);
            float4 msg;
            msg.x = f.x * filt[e].x;
            msg.y = f.y * filt[e].y;
            msg.z = f.z * filt[e].z;
            msg.w = f.w * filt[e].w;
            if (si != cur_seg) {
                if (cur_seg >= 0) {
                    float* o = outb + (size_t)cur_seg * DCH + c0;
                    atomicAdd(o + 0, racc.x);
                    atomicAdd(o + 1, racc.y);
                    atomicAdd(o + 2, racc.z);
                    atomicAdd(o + 3, racc.w);
                }
                cur_seg = si;
                racc = msg;
            } else {
                racc.x += msg.x; racc.y += msg.y; racc.z += msg.z; racc.w += msg.w;
            }
        }
    }

    if (cur_seg >= 0) {
        float* o = outb + (size_t)cur_seg * DCH + c0;
        atomicAdd(o + 0, racc.x);
        atomicAdd(o + 1, racc.y);
        atomicAdd(o + 2, racc.z);
        atomicAdd(o + 3, racc.w);
    }
}

extern "C" void kernel_launch(void* const* d_in, const int* in_sizes, int n_in,
                              void* d_out, int out_size) {
    const float* atom    = (const float*)d_in[0];
    const float* dist    = (const float*)d_in[1];
    const int*   idx_j   = (const int*)  d_in[2];
    const int*   seg_i   = (const int*)  d_in[3];
    const float* centers = (const float*)d_in[4];
    const float* gammav  = (const float*)d_in[5];
    const float* W1      = (const float*)d_in[6];
    const float* b1      = (const float*)d_in[7];
    const float* W2      = (const float*)d_in[8];
    const float* b2      = (const float*)d_in[9];
    float* out = (float*)d_out;

    (void)in_sizes; (void)n_in;

    static_assert(SMEM_FLOATS * 4 == 122880, "smem layout");
    cudaFuncSetAttribute(cfconv_kernel,
                         cudaFuncAttributeMaxDynamicSharedMemorySize,
                         SMEM_FLOATS * sizeof(float));

    // Output is poisoned by the harness; atomics need zeros.
    cudaMemsetAsync(d_out, 0, (size_t)out_size * sizeof(float), 0);

    cfconv_kernel<<<BLOCKS, TPB, SMEM_FLOATS * sizeof(float)>>>(
        atom, dist, idx_j, seg_i, centers, gammav, W1, b1, W2, b2, out);
}

// round 3
// speedup vs baseline: 1.5901x; 1.5901x over previous
#include <cuda_runtime.h>

// Problem constants (fixed by the dataset)
#define NB      2
#define NATOMS  25000
#define NE      400000
#define DCH     128
#define NRBF    64
#define CUTOFF  15.0f

// Distance -> h1 lookup table (replaces GEMM1): h1(d) = ssp(rbf(d)@W1 + b1)
#define TABN    8192                      // intervals; TABN+1 grid points
__device__ float g_table[(TABN + 1) * DCH];   // 4.2 MB scratch (static, allowed)

// Launch config (main kernel)
#define BLOCKS  296
#define TPB     256
#define WPB     (TPB/32)                   // 8 warps
#define TOTAL_WARPS (BLOCKS*WPB)           // 2368
#define WARPS_PER_BATCH (TOTAL_WARPS/NB)   // 1184
#define ETILE   16
#define CHUNK   352                        // 22 tiles; 1184*352 >= 400000

// Dynamic smem: W2 (128x128 f32) + per-warp duplicated h1 tiles
//   W2s : 16384 floats
//   h1d : 8 warps * 16 edges * 256 floats (each h1 value stored twice: {h,h})
#define SMEM_FLOATS (16384 + WPB*ETILE*256)   // 49152 floats = 196608 B

__device__ __forceinline__ float ssp(float x) {
    float ax = fabsf(x);
    return fmaxf(x, 0.f) + __logf(1.f + __expf(-ax)) - 0.69314718056f;
}

__device__ __forceinline__ unsigned long long ffma2(unsigned long long a,
                                                    unsigned long long b,
                                                    unsigned long long c) {
    unsigned long long d;
    asm("fma.rn.f32x2 %0, %1, %2, %3;" : "=l"(d) : "l"(a), "l"(b), "l"(c));
    return d;
}

// ---------------- table build: h1[i][c] = ssp(sum_k exp(-g(x_i-c_k)^2) W1[k][c] + b1[c])
__global__ void build_table_kernel(const float* __restrict__ centers,
                                   const float* __restrict__ gammav,
                                   const float* __restrict__ W1,
                                   const float* __restrict__ b1) {
    __shared__ float rbf[NRBF];
    const int i = blockIdx.x;                 // grid point
    const int c = threadIdx.x;                // channel
    const float x = (float)i * (CUTOFF / (float)TABN);
    if (c < NRBF) {
        float t = x - centers[c];
        rbf[c] = __expf(-gammav[c] * t * t);
    }
    __syncthreads();
    float acc = b1[c];
    #pragma unroll
    for (int k = 0; k < NRBF; k++)
        acc = fmaf(rbf[k], W1[k * DCH + c], acc);
    g_table[i * DCH + c] = ssp(acc);
}

// ---------------- main kernel
__global__ __launch_bounds__(TPB, 1)
void cfconv_kernel(const float* __restrict__ atom,      // [B, N, D]
                   const float* __restrict__ dist,      // [B, E]
                   const int*   __restrict__ idx_j,     // [E]
                   const int*   __restrict__ seg_i,     // [E] sorted
                   const float* __restrict__ W2,        // [D, D]
                   const float* __restrict__ b2,        // [D]
                   float*       __restrict__ out)       // [B, N, D] zeroed
{
    extern __shared__ float sm[];
    float* W2s = sm;                     // 16384 floats
    float* h1s = sm + 16384;             // WPB * 16 * 256

    const int tid = threadIdx.x;
    for (int i = tid; i < DCH * DCH; i += TPB) W2s[i] = W2[i];
    __syncthreads();

    const int wib  = tid >> 5;
    const int lane = tid & 31;
    const int c0   = lane * 4;
    float* h1w = h1s + wib * (ETILE * 256);   // this warp's dup-h1 tile

    const unsigned long long bb2a = *(const unsigned long long*)(b2 + c0);
    const unsigned long long bb2b = *(const unsigned long long*)(b2 + c0 + 2);

    const int  gw = blockIdx.x * WPB + wib;
    const int  b  = gw / WARPS_PER_BATCH;
    long e0    = (long)(gw % WARPS_PER_BATCH) * CHUNK;
    long e_end = e0 + CHUNK; if (e_end > NE) e_end = NE;

    const float* distb = dist + (size_t)b * NE;
    const float* atomb = atom + (size_t)b * NATOMS * DCH;
    float*       outb  = out  + (size_t)b * NATOMS * DCH;

    int    cur_seg = -1;
    float4 racc    = make_float4(0.f, 0.f, 0.f, 0.f);
    const float inv_h = (float)TABN / CUTOFF;

    for (long base = e0; base < e_end; base += ETILE) {
        const int m = (int)((e_end - base) < ETILE ? (e_end - base) : ETILE);

        // ---- phase 1: table lerp -> duplicated h1 tile in smem ----
        #pragma unroll
        for (int e = 0; e < ETILE; e++) {
            long ge = base + (e < m ? e : m - 1);
            float d = distb[ge];
            float t = d * inv_h;
            int   i = (int)t;
            i = i < 0 ? 0 : (i > TABN - 1 ? TABN - 1 : i);
            float f = t - (float)i;
            const float* r0 = g_table + (size_t)i * DCH + c0;
            float4 a  = *(const float4*)(r0);
            float4 bq = *(const float4*)(r0 + DCH);
            float4 h;
            h.x = fmaf(f, bq.x - a.x, a.x);
            h.y = fmaf(f, bq.y - a.y, a.y);
            h.z = fmaf(f, bq.z - a.z, a.z);
            h.w = fmaf(f, bq.w - a.w, a.w);
            float* dstp = h1w + e * 256 + 8 * lane;
            *(float4*)(dstp)     = make_float4(h.x, h.x, h.y, h.y);
            *(float4*)(dstp + 4) = make_float4(h.z, h.z, h.w, h.w);
        }
        __syncwarp();

        // ---- phase 2: filters_pre = h1 @ W2 + b2 (f32x2 packed) ----
        ulonglong2 acc[ETILE];
        #pragma unroll
        for (int e = 0; e < ETILE; e++) { acc[e].x = bb2a; acc[e].y = bb2b; }

        #pragma unroll 2
        for (int t = 0; t < DCH / 4; t++) {
            const ulonglong2 w0 = *(const ulonglong2*)(W2s + (4*t + 0) * DCH + c0);
            const ulonglong2 w1 = *(const ulonglong2*)(W2s + (4*t + 1) * DCH + c0);
            const ulonglong2 w2 = *(const ulonglong2*)(W2s + (4*t + 2) * DCH + c0);
            const ulonglong2 w3 = *(const ulonglong2*)(W2s + (4*t + 3) * DCH + c0);
            #pragma unroll
            for (int e = 0; e < ETILE; e++) {
                const float* hp = h1w + e * 256 + 8 * t;
                const ulonglong2 hA = *(const ulonglong2*)(hp);      // {h0,h0},{h1,h1}
                const ulonglong2 hB = *(const ulonglong2*)(hp + 4);  // {h2,h2},{h3,h3}
                acc[e].x = ffma2(hA.x, w0.x, acc[e].x);
                acc[e].y = ffma2(hA.x, w0.y, acc[e].y);
                acc[e].x = ffma2(hA.y, w1.x, acc[e].x);
                acc[e].y = ffma2(hA.y, w1.y, acc[e].y);
                acc[e].x = ffma2(hB.x, w2.x, acc[e].x);
                acc[e].y = ffma2(hB.x, w2.y, acc[e].y);
                acc[e].x = ffma2(hB.y, w3.x, acc[e].x);
                acc[e].y = ffma2(hB.y, w3.y, acc[e].y);
            }
        }
        __syncwarp();

        // ---- phase 3: ssp, gather, multiply, run-length segment accumulate ----
        #pragma unroll
        for (int e = 0; e < ETILE; e++) {
            if (e >= m) break;
            long ge = base + e;
            int  aj = idx_j[ge];
            int  si = seg_i[ge];
            float2 lo = *reinterpret_cast<float2*>(&acc[e].x);
            float2 hi = *reinterpret_cast<float2*>(&acc[e].y);
            float4 filt;
            filt.x = ssp(lo.x); filt.y = ssp(lo.y);
            filt.z = ssp(hi.x); filt.w = ssp(hi.y);
            float4 f = *(const float4*)(atomb + (size_t)aj * DCH + c0);
            float4 msg;
            msg.x = f.x * filt.x; msg.y = f.y * filt.y;
            msg.z = f.z * filt.z; msg.w = f.w * filt.w;
            if (si != cur_seg) {
                if (cur_seg >= 0) {
                    float* o = outb + (size_t)cur_seg * DCH + c0;
                    atomicAdd(o + 0, racc.x);
                    atomicAdd(o + 1, racc.y);
                    atomicAdd(o + 2, racc.z);
                    atomicAdd(o + 3, racc.w);
                }
                cur_seg = si;
                racc = msg;
            } else {
                racc.x += msg.x; racc.y += msg.y;
                racc.z += msg.z; racc.w += msg.w;
            }
        }
    }

    if (cur_seg >= 0) {
        float* o = outb + (size_t)cur_seg * DCH + c0;
        atomicAdd(o + 0, racc.x);
        atomicAdd(o + 1, racc.y);
        atomicAdd(o + 2, racc.z);
        atomicAdd(o + 3, racc.w);
    }
}

extern "C" void kernel_launch(void* const* d_in, const int* in_sizes, int n_in,
                              void* d_out, int out_size) {
    const float* atom    = (const float*)d_in[0];
    const float* dist    = (const float*)d_in[1];
    const int*   idx_j   = (const int*)  d_in[2];
    const int*   seg_i   = (const int*)  d_in[3];
    const float* centers = (const float*)d_in[4];
    const float* gammav  = (const float*)d_in[5];
    const float* W1      = (const float*)d_in[6];
    const float* b1      = (const float*)d_in[7];
    const float* W2      = (const float*)d_in[8];
    const float* b2      = (const float*)d_in[9];
    float* out = (float*)d_out;

    (void)in_sizes; (void)n_in;

    cudaFuncSetAttribute(cfconv_kernel,
                         cudaFuncAttributeMaxDynamicSharedMemorySize,
                         SMEM_FLOATS * sizeof(float));

    // 1) build h1(d) lookup table
    build_table_kernel<<<TABN + 1, DCH>>>(centers, gammav, W1, b1);
    // 2) zero output (harness poisons it; atomics need zeros)
    cudaMemsetAsync(d_out, 0, (size_t)out_size * sizeof(float), 0);
    // 3) main fused kernel
    cfconv_kernel<<<BLOCKS, TPB, SMEM_FLOATS * sizeof(float)>>>(
        atom, dist, idx_j, seg_i, W2, b2, out);
}